// round 1
// baseline (speedup 1.0000x reference)
#include <cuda_runtime.h>

// Problem constants (shapes fixed by the dataset)
#define NN   40000
#define EE   640000
#define FIN  128
#define FHID 256
#define FCLS 40

// ---- scratch (no allocation allowed -> __device__ globals) ----
__device__ int   g_deg[NN];
__device__ int   g_rowptr[NN + 1];
__device__ int   g_cur[NN];
__device__ int   g_colidx[EE];
__device__ float g_norm[NN];
__device__ float g_norm2[NN];
__device__ float g_buf1[NN * FIN];
__device__ float g_buf2[NN * FIN];
__device__ float g_bufh[NN * FHID];

// ---------------------------------------------------------------
// 1. zero degree
__global__ void zero_deg_kernel() {
    int i = blockIdx.x * blockDim.x + threadIdx.x;
    if (i < NN) g_deg[i] = 0;
}

// 2. degree histogram (in-degree over dst)
__global__ void count_deg_kernel(const int* __restrict__ dst) {
    int e = blockIdx.x * blockDim.x + threadIdx.x;
    if (e < EE) atomicAdd(&g_deg[dst[e]], 1);
}

// 3. single-block exclusive scan over 40000 counts.
//    Also emits cursor copy and norm / norm^2.
__global__ void scan_build_kernel() {
    __shared__ int partials[1024];
    const int tid = threadIdx.x;
    const int CH  = (NN + 1023) / 1024;   // 40
    const int start = tid * CH;

    int sum = 0;
    for (int i = 0; i < CH; i++) {
        int idx = start + i;
        if (idx < NN) sum += g_deg[idx];
    }
    partials[tid] = sum;
    __syncthreads();

    // Hillis-Steele inclusive scan over 1024 partials
    for (int off = 1; off < 1024; off <<= 1) {
        int v = 0;
        if (tid >= off) v = partials[tid - off];
        __syncthreads();
        partials[tid] += v;
        __syncthreads();
    }

    int run = (tid > 0) ? partials[tid - 1] : 0;  // exclusive base
    for (int i = 0; i < CH; i++) {
        int idx = start + i;
        if (idx < NN) {
            g_rowptr[idx] = run;
            g_cur[idx]    = run;
            int d = g_deg[idx];
            run += d;
            float dn = fmaxf((float)d, 1.0f);
            float nv = rsqrtf(dn);
            g_norm[idx]  = nv;
            g_norm2[idx] = nv * nv;
        }
    }
    if (tid == 0) g_rowptr[NN] = partials[1023];
}

// 4. fill CSR column indices (source node per edge, grouped by dst)
__global__ void fill_csr_kernel(const int* __restrict__ src,
                                const int* __restrict__ dst) {
    int e = blockIdx.x * blockDim.x + threadIdx.x;
    if (e < EE) {
        int p = atomicAdd(&g_cur[dst[e]], 1);
        g_colidx[p] = src[e];
    }
}

// 5. one propagation hop: warp per dst node, lane handles one float4 (128 floats).
//    hout[w] = sum_{edges (s->w)} hin[s] * scale[s]
__global__ void hop_kernel(const float* __restrict__ hin,
                           float* __restrict__ hout,
                           const float* __restrict__ scale) {
    int w    = (blockIdx.x * blockDim.x + threadIdx.x) >> 5;
    int lane = threadIdx.x & 31;
    if (w >= NN) return;

    int jb = g_rowptr[w];
    int je = g_rowptr[w + 1];

    const float4* hin4 = (const float4*)hin;
    float4 acc = make_float4(0.f, 0.f, 0.f, 0.f);
    for (int j = jb; j < je; j++) {
        int   s  = g_colidx[j];
        float sc = __ldg(&scale[s]);
        float4 v = hin4[s * 32 + lane];
        acc.x = fmaf(v.x, sc, acc.x);
        acc.y = fmaf(v.y, sc, acc.y);
        acc.z = fmaf(v.z, sc, acc.z);
        acc.w = fmaf(v.w, sc, acc.w);
    }
    ((float4*)hout)[w * 32 + lane] = acc;
}

// 6. GEMM1: H = relu((buf2 * norm_row) @ W1 + b1)   [N,128]x[128,256]
//    block = 256 threads, tile = 64 rows x 256 cols, K-chunks of 32.
__global__ void gemm1_kernel(const float* __restrict__ A,
                             const float* __restrict__ W1,
                             const float* __restrict__ b1,
                             float* __restrict__ H) {
    __shared__ float As[32 * 65];    // [k][r] padded
    __shared__ float Bs[32 * 256];   // [k][c]

    const int tid  = threadIdx.x;
    const int row0 = blockIdx.x * 64;
    const int tx   = tid & 15;       // col lane (consecutive cols)
    const int ty   = tid >> 4;       // row group

    float acc[4][16];
#pragma unroll
    for (int i = 0; i < 4; i++)
#pragma unroll
        for (int c = 0; c < 16; c++) acc[i][c] = 0.f;

    for (int kk = 0; kk < 4; kk++) {
        // stage A chunk (transposed, with per-row norm folded in)
#pragma unroll
        for (int l = 0; l < 8; l++) {
            int e = tid + l * 256;
            int r = e >> 5, k = e & 31;
            int grow = row0 + r;
            As[k * 65 + r] = A[grow * FIN + kk * 32 + k] * g_norm[grow];
        }
        // stage W1 chunk (contiguous 32x256 block)
        {
            const float4* W14 = (const float4*)(W1 + kk * 32 * FHID);
            float4* Bs4 = (float4*)Bs;
#pragma unroll
            for (int l = 0; l < 8; l++) Bs4[tid + l * 256] = W14[tid + l * 256];
        }
        __syncthreads();

#pragma unroll
        for (int k = 0; k < 32; k++) {
            float a[4], b[16];
#pragma unroll
            for (int i = 0; i < 4; i++) a[i] = As[k * 65 + ty * 4 + i];
#pragma unroll
            for (int c = 0; c < 16; c++) b[c] = Bs[k * 256 + c * 16 + tx];
#pragma unroll
            for (int i = 0; i < 4; i++)
#pragma unroll
                for (int c = 0; c < 16; c++) acc[i][c] = fmaf(a[i], b[c], acc[i][c]);
        }
        __syncthreads();
    }

#pragma unroll
    for (int i = 0; i < 4; i++) {
        int grow = row0 + ty * 4 + i;
#pragma unroll
        for (int c = 0; c < 16; c++) {
            int col = c * 16 + tx;
            float v = acc[i][c] + b1[col];
            H[grow * FHID + col] = fmaxf(v, 0.f);
        }
    }
}

// 7. GEMM2: out = H @ W2 + b2   [N,256]x[256,40]
//    block = 256 threads, tile = 64 rows; thread: (row, colgroup of 10)
__global__ void gemm2_kernel(const float* __restrict__ H,
                             const float* __restrict__ W2,
                             const float* __restrict__ b2,
                             float* __restrict__ out) {
    __shared__ float HsT[32 * 65];   // [k][r] padded
    __shared__ float W2s[32 * 40];   // [k][c]

    const int tid  = threadIdx.x;
    const int row0 = blockIdx.x * 64;
    const int r    = tid >> 2;       // 0..63
    const int cg   = tid & 3;        // 0..3, 10 cols each

    float acc[10];
#pragma unroll
    for (int c = 0; c < 10; c++) acc[c] = 0.f;

    for (int kk = 0; kk < 8; kk++) {
#pragma unroll
        for (int l = 0; l < 8; l++) {
            int e = tid + l * 256;
            int rr = e >> 5, k = e & 31;
            HsT[k * 65 + rr] = H[(row0 + rr) * FHID + kk * 32 + k];
        }
#pragma unroll
        for (int l = 0; l < 5; l++) {
            int e = tid + l * 256;
            W2s[e] = W2[kk * 32 * FCLS + e];
        }
        __syncthreads();

#pragma unroll
        for (int k = 0; k < 32; k++) {
            float a = HsT[k * 65 + r];
#pragma unroll
            for (int c = 0; c < 10; c++)
                acc[c] = fmaf(a, W2s[k * FCLS + cg * 10 + c], acc[c]);
        }
        __syncthreads();
    }

    int grow = row0 + r;
#pragma unroll
    for (int c = 0; c < 10; c++) {
        int col = cg * 10 + c;
        out[grow * FCLS + col] = acc[c] + b2[col];
    }
}

// ---------------------------------------------------------------
extern "C" void kernel_launch(void* const* d_in, const int* in_sizes, int n_in,
                              void* d_out, int out_size) {
    const float* features = (const float*)d_in[0];
    const int*   src      = (const int*)d_in[1];
    const int*   dst      = (const int*)d_in[2];
    const float* W1       = (const float*)d_in[3];
    const float* b1       = (const float*)d_in[4];
    const float* W2       = (const float*)d_in[5];
    const float* b2       = (const float*)d_in[6];
    float*       out      = (float*)d_out;

    float *buf1, *buf2, *bufh, *norm, *norm2;
    cudaGetSymbolAddress((void**)&buf1,  g_buf1);
    cudaGetSymbolAddress((void**)&buf2,  g_buf2);
    cudaGetSymbolAddress((void**)&bufh,  g_bufh);
    cudaGetSymbolAddress((void**)&norm,  g_norm);
    cudaGetSymbolAddress((void**)&norm2, g_norm2);

    // CSR build
    zero_deg_kernel<<<(NN + 255) / 256, 256>>>();
    count_deg_kernel<<<(EE + 255) / 256, 256>>>(dst);
    scan_build_kernel<<<1, 1024>>>();
    fill_csr_kernel<<<(EE + 255) / 256, 256>>>(src, dst);

    // 2 hops (norms folded into per-source scale; final row-norm folded into GEMM1)
    hop_kernel<<<(NN * 32 + 255) / 256, 256>>>(features, buf1, norm);
    hop_kernel<<<(NN * 32 + 255) / 256, 256>>>(buf1, buf2, norm2);

    // MLP head
    gemm1_kernel<<<NN / 64, 256>>>(buf2, W1, b1, bufh);
    gemm2_kernel<<<NN / 64, 256>>>(bufh, W2, b2, out);
}

// round 3
// speedup vs baseline: 1.4468x; 1.4468x over previous
#include <cuda_runtime.h>
#include <cstdint>

#define NN   40000
#define EE   640000
#define FIN  128
#define FHID 256
#define FCLS 40

// ---- scratch (no allocation allowed -> __device__ globals) ----
__device__ int   g_deg[NN];
__device__ int   g_rowptr[NN + 1];
__device__ int   g_cur[NN];
__device__ int   g_colidx[EE];
__device__ float g_norm[NN];
__device__ float g_norm2[NN];
__device__ float g_buf1[NN * FIN];
__device__ float g_buf2[NN * FIN];
__device__ float g_bufh[NN * FHID];

// ---------------------------------------------------------------
__device__ __forceinline__ unsigned f2tf32(float x) {
    unsigned r;
    asm("cvt.rna.tf32.f32 %0, %1;" : "=r"(r) : "f"(x));
    return r;
}

__device__ __forceinline__ void mma_tf32(float c[4],
                                         unsigned a0, unsigned a1, unsigned a2, unsigned a3,
                                         unsigned b0, unsigned b1) {
    asm volatile(
        "mma.sync.aligned.m16n8k8.row.col.f32.tf32.tf32.f32 "
        "{%0,%1,%2,%3}, {%4,%5,%6,%7}, {%8,%9}, {%0,%1,%2,%3};"
        : "+f"(c[0]), "+f"(c[1]), "+f"(c[2]), "+f"(c[3])
        : "r"(a0), "r"(a1), "r"(a2), "r"(a3), "r"(b0), "r"(b1));
}

// ---------------------------------------------------------------
// 1. zero degree
__global__ void zero_deg_kernel() {
    int i = blockIdx.x * blockDim.x + threadIdx.x;
    if (i < NN) g_deg[i] = 0;
}

// 2. degree histogram (in-degree over dst)
__global__ void count_deg_kernel(const int* __restrict__ dst) {
    int e = blockIdx.x * blockDim.x + threadIdx.x;
    if (e < EE) atomicAdd(&g_deg[dst[e]], 1);
}

// 3. single-block exclusive scan over 40000 counts + norms.
__global__ void scan_build_kernel() {
    __shared__ int partials[1024];
    const int tid = threadIdx.x;
    const int CH  = (NN + 1023) / 1024;   // 40
    const int start = tid * CH;

    int sum = 0;
    for (int i = 0; i < CH; i++) {
        int idx = start + i;
        if (idx < NN) sum += g_deg[idx];
    }
    partials[tid] = sum;
    __syncthreads();

    for (int off = 1; off < 1024; off <<= 1) {
        int v = 0;
        if (tid >= off) v = partials[tid - off];
        __syncthreads();
        partials[tid] += v;
        __syncthreads();
    }

    int run = (tid > 0) ? partials[tid - 1] : 0;
    for (int i = 0; i < CH; i++) {
        int idx = start + i;
        if (idx < NN) {
            g_rowptr[idx] = run;
            g_cur[idx]    = run;
            int d = g_deg[idx];
            run += d;
            float dn = fmaxf((float)d, 1.0f);
            float nv = rsqrtf(dn);
            g_norm[idx]  = nv;
            g_norm2[idx] = nv * nv;
        }
    }
    if (tid == 0) g_rowptr[NN] = partials[1023];
}

// 4. fill CSR column indices
__global__ void fill_csr_kernel(const int* __restrict__ src,
                                const int* __restrict__ dst) {
    int e = blockIdx.x * blockDim.x + threadIdx.x;
    if (e < EE) {
        int p = atomicAdd(&g_cur[dst[e]], 1);
        g_colidx[p] = src[e];
    }
}

// 5. propagation hop: warp per dst node, lane = one float4 (128 floats/row).
//    hout[w] = wscale[w] * sum_{(s->w)} hin[s] * sscale[s]
__global__ void hop_kernel(const float* __restrict__ hin,
                           float* __restrict__ hout,
                           const float* __restrict__ sscale,
                           const float* __restrict__ wscale) {
    int w    = (blockIdx.x * blockDim.x + threadIdx.x) >> 5;
    int lane = threadIdx.x & 31;
    if (w >= NN) return;

    int jb = g_rowptr[w];
    int je = g_rowptr[w + 1];

    const float4* hin4 = (const float4*)hin;
    float4 acc = make_float4(0.f, 0.f, 0.f, 0.f);
    for (int j = jb; j < je; j++) {
        int   s  = g_colidx[j];
        float sc = __ldg(&sscale[s]);
        float4 v = hin4[s * 32 + lane];
        acc.x = fmaf(v.x, sc, acc.x);
        acc.y = fmaf(v.y, sc, acc.y);
        acc.z = fmaf(v.z, sc, acc.z);
        acc.w = fmaf(v.w, sc, acc.w);
    }
    if (wscale) {
        float ws = wscale[w];
        acc.x *= ws; acc.y *= ws; acc.z *= ws; acc.w *= ws;
    }
    ((float4*)hout)[w * 32 + lane] = acc;
}

// ---------------------------------------------------------------
// 6. GEMM1 (tf32 tensor cores): H = relu(A @ W1 + b1), A=[N,128], W1=[128,256]
//    block 256 thr = 8 warps (2x4), tile M=64, N=256, K-chunks of 32.
#define AS_STRIDE 36    // 36 % 32 == 4 -> conflict-free frag loads
#define BS_STRIDE 264   // 264 % 32 == 8 -> conflict-free frag loads

__global__ __launch_bounds__(256) void gemm1_mma(const float* __restrict__ A,
                                                 const float* __restrict__ W1,
                                                 const float* __restrict__ b1,
                                                 float* __restrict__ H) {
    __shared__ float As[64 * AS_STRIDE];
    __shared__ float Bs[32 * BS_STRIDE];

    const int tid  = threadIdx.x;
    const int lane = tid & 31;
    const int warp = tid >> 5;
    const int wm   = warp >> 2;        // 0..1
    const int wn   = warp & 3;         // 0..3
    const int row0 = blockIdx.x * 64;
    const int g    = lane >> 2;        // 0..7
    const int tk   = lane & 3;         // 0..3

    float c[2][8][4];
#pragma unroll
    for (int i = 0; i < 2; i++)
#pragma unroll
        for (int j = 0; j < 8; j++)
#pragma unroll
            for (int q = 0; q < 4; q++) c[i][j][q] = 0.f;

    for (int kk = 0; kk < 4; kk++) {
        // stage A chunk: 64 x 32 (converted to tf32 once)
#pragma unroll
        for (int l = 0; l < 2; l++) {
            int f  = tid + l * 256;        // 0..511 float4s
            int r  = f >> 3;
            int c4 = (f & 7) * 4;
            float4 v = *(const float4*)(A + (row0 + r) * FIN + kk * 32 + c4);
            float* dst = &As[r * AS_STRIDE + c4];
            dst[0] = __uint_as_float(f2tf32(v.x));
            dst[1] = __uint_as_float(f2tf32(v.y));
            dst[2] = __uint_as_float(f2tf32(v.z));
            dst[3] = __uint_as_float(f2tf32(v.w));
        }
        // stage W1 chunk: 32 x 256
#pragma unroll
        for (int l = 0; l < 8; l++) {
            int f  = tid + l * 256;        // 0..2047 float4s
            int r  = f >> 6;
            int c4 = (f & 63) * 4;
            float4 v = *(const float4*)(W1 + (kk * 32 + r) * FHID + c4);
            float* dst = &Bs[r * BS_STRIDE + c4];
            dst[0] = __uint_as_float(f2tf32(v.x));
            dst[1] = __uint_as_float(f2tf32(v.y));
            dst[2] = __uint_as_float(f2tf32(v.z));
            dst[3] = __uint_as_float(f2tf32(v.w));
        }
        __syncthreads();

#pragma unroll
        for (int k8 = 0; k8 < 4; k8++) {
            int kl = k8 * 8 + tk;
            unsigned a[2][4];
#pragma unroll
            for (int mt = 0; mt < 2; mt++) {
                int rb = wm * 32 + mt * 16 + g;
                a[mt][0] = __float_as_uint(As[rb * AS_STRIDE + kl]);
                a[mt][1] = __float_as_uint(As[(rb + 8) * AS_STRIDE + kl]);
                a[mt][2] = __float_as_uint(As[rb * AS_STRIDE + kl + 4]);
                a[mt][3] = __float_as_uint(As[(rb + 8) * AS_STRIDE + kl + 4]);
            }
            unsigned b[8][2];
#pragma unroll
            for (int nt = 0; nt < 8; nt++) {
                int n = wn * 64 + nt * 8 + g;
                b[nt][0] = __float_as_uint(Bs[kl * BS_STRIDE + n]);
                b[nt][1] = __float_as_uint(Bs[(kl + 4) * BS_STRIDE + n]);
            }
#pragma unroll
            for (int mt = 0; mt < 2; mt++)
#pragma unroll
                for (int nt = 0; nt < 8; nt++)
                    mma_tf32(c[mt][nt], a[mt][0], a[mt][1], a[mt][2], a[mt][3],
                             b[nt][0], b[nt][1]);
        }
        __syncthreads();
    }

    // epilogue: bias + relu, float2 stores
#pragma unroll
    for (int mt = 0; mt < 2; mt++) {
        int r0 = row0 + wm * 32 + mt * 16 + g;
#pragma unroll
        for (int nt = 0; nt < 8; nt++) {
            int col = wn * 64 + nt * 8 + (tk << 1);
            float bb0 = b1[col], bb1 = b1[col + 1];
            float2 v0 = make_float2(fmaxf(c[mt][nt][0] + bb0, 0.f),
                                    fmaxf(c[mt][nt][1] + bb1, 0.f));
            float2 v1 = make_float2(fmaxf(c[mt][nt][2] + bb0, 0.f),
                                    fmaxf(c[mt][nt][3] + bb1, 0.f));
            *(float2*)(H + r0 * FHID + col)       = v0;
            *(float2*)(H + (r0 + 8) * FHID + col) = v1;
        }
    }
}

// ---------------------------------------------------------------
// 7. GEMM2 (tf32): out = H @ W2 + b2, H=[N,256], W2=[256,40]
//    block 256 thr = 8 warps, tile M=128 (warp = m16 band), N=40 (5 n8 tiles)
#define HS_STRIDE 36   // 36 % 32 == 4

__global__ __launch_bounds__(256) void gemm2_mma(const float* __restrict__ H,
                                                 const float* __restrict__ W2,
                                                 const float* __restrict__ b2,
                                                 float* __restrict__ out) {
    __shared__ float Hs[128 * HS_STRIDE];
    __shared__ float Ws[32 * FCLS];    // stride 40: 40%32==8 -> conflict-free

    const int tid  = threadIdx.x;
    const int lane = tid & 31;
    const int warp = tid >> 5;
    const int row0 = blockIdx.x * 128;
    const int g    = lane >> 2;
    const int tk   = lane & 3;

    float c[5][4];
#pragma unroll
    for (int j = 0; j < 5; j++)
#pragma unroll
        for (int q = 0; q < 4; q++) c[j][q] = 0.f;

    for (int kk = 0; kk < 8; kk++) {
        // stage H chunk: 128 x 32 (guarded)
#pragma unroll
        for (int l = 0; l < 4; l++) {
            int f  = tid + l * 256;        // 0..1023 float4s
            int r  = f >> 3;
            int c4 = (f & 7) * 4;
            int grow = row0 + r;
            float4 v = make_float4(0.f, 0.f, 0.f, 0.f);
            if (grow < NN) v = *(const float4*)(H + grow * FHID + kk * 32 + c4);
            float* dst = &Hs[r * HS_STRIDE + c4];
            dst[0] = __uint_as_float(f2tf32(v.x));
            dst[1] = __uint_as_float(f2tf32(v.y));
            dst[2] = __uint_as_float(f2tf32(v.z));
            dst[3] = __uint_as_float(f2tf32(v.w));
        }
        // stage W2 chunk: 32 x 40 = 320 float4s
#pragma unroll
        for (int l = 0; l < 2; l++) {
            int f = tid + l * 256;
            if (f < 320) {
                int r  = f / 10;
                int c4 = (f % 10) * 4;
                float4 v = *(const float4*)(W2 + (kk * 32 + r) * FCLS + c4);
                float* dst = &Ws[r * FCLS + c4];
                dst[0] = __uint_as_float(f2tf32(v.x));
                dst[1] = __uint_as_float(f2tf32(v.y));
                dst[2] = __uint_as_float(f2tf32(v.z));
                dst[3] = __uint_as_float(f2tf32(v.w));
            }
        }
        __syncthreads();

#pragma unroll
        for (int k8 = 0; k8 < 4; k8++) {
            int kl = k8 * 8 + tk;
            int rb = warp * 16 + g;
            unsigned a0 = __float_as_uint(Hs[rb * HS_STRIDE + kl]);
            unsigned a1 = __float_as_uint(Hs[(rb + 8) * HS_STRIDE + kl]);
            unsigned a2 = __float_as_uint(Hs[rb * HS_STRIDE + kl + 4]);
            unsigned a3 = __float_as_uint(Hs[(rb + 8) * HS_STRIDE + kl + 4]);
#pragma unroll
            for (int nt = 0; nt < 5; nt++) {
                unsigned b0 = __float_as_uint(Ws[kl * FCLS + nt * 8 + g]);
                unsigned b1 = __float_as_uint(Ws[(kl + 4) * FCLS + nt * 8 + g]);
                mma_tf32(c[nt], a0, a1, a2, a3, b0, b1);
            }
        }
        __syncthreads();
    }

    int r0 = row0 + warp * 16 + g;
#pragma unroll
    for (int nt = 0; nt < 5; nt++) {
        int col = nt * 8 + (tk << 1);
        float bb0 = b2[col], bb1 = b2[col + 1];
        if (r0 < NN)
            *(float2*)(out + r0 * FCLS + col) =
                make_float2(c[nt][0] + bb0, c[nt][1] + bb1);
        if (r0 + 8 < NN)
            *(float2*)(out + (r0 + 8) * FCLS + col) =
                make_float2(c[nt][2] + bb0, c[nt][3] + bb1);
    }
}

// ---------------------------------------------------------------
extern "C" void kernel_launch(void* const* d_in, const int* in_sizes, int n_in,
                              void* d_out, int out_size) {
    const float* features = (const float*)d_in[0];
    const int*   src      = (const int*)d_in[1];
    const int*   dst      = (const int*)d_in[2];
    const float* W1       = (const float*)d_in[3];
    const float* b1       = (const float*)d_in[4];
    const float* W2       = (const float*)d_in[5];
    const float* b2       = (const float*)d_in[6];
    float*       out      = (float*)d_out;

    float *buf1, *buf2, *bufh, *norm, *norm2;
    cudaGetSymbolAddress((void**)&buf1,  g_buf1);
    cudaGetSymbolAddress((void**)&buf2,  g_buf2);
    cudaGetSymbolAddress((void**)&bufh,  g_bufh);
    cudaGetSymbolAddress((void**)&norm,  g_norm);
    cudaGetSymbolAddress((void**)&norm2, g_norm2);

    // CSR build
    zero_deg_kernel<<<(NN + 255) / 256, 256>>>();
    count_deg_kernel<<<(EE + 255) / 256, 256>>>(dst);
    scan_build_kernel<<<1, 1024>>>();
    fill_csr_kernel<<<(EE + 255) / 256, 256>>>(src, dst);

    // 2 hops: hop1 scale=norm[src]; hop2 scale=norm^2[src], out-scale=norm[dst]
    hop_kernel<<<(NN * 32 + 255) / 256, 256>>>(features, buf1, norm, nullptr);
    hop_kernel<<<(NN * 32 + 255) / 256, 256>>>(buf1, buf2, norm2, norm);

    // MLP head on tensor cores (tf32)
    gemm1_mma<<<NN / 64, 256>>>(buf2, W1, b1, bufh);
    gemm2_mma<<<(NN + 127) / 128, 256>>>(bufh, W2, b2, out);
}

// round 4
// speedup vs baseline: 1.5830x; 1.0941x over previous
#include <cuda_runtime.h>
#include <cuda_fp16.h>
#include <cstdint>

#define NN   40000
#define EE   640000
#define FIN  128
#define FHID 256
#define FCLS 40

// ---- scratch (no allocation allowed -> __device__ globals) ----
__device__ int    g_deg[NN];
__device__ int    g_rowptr[NN + 1];
__device__ int    g_cur[NN];
__device__ int    g_colidx[EE];
__device__ float  g_norm[NN];
__device__ float  g_norm2[NN];
__device__ __half g_feat_h[NN * FIN];   // norm * X      (fp16)
__device__ __half g_buf1h[NN * FIN];    // N^2 A N X     (fp16)
__device__ float  g_buf2[NN * FIN];     // N A N^2 A N X (fp32, GEMM input)

// ---------------------------------------------------------------
__device__ __forceinline__ unsigned f2tf32(float x) {
    unsigned r;
    asm("cvt.rna.tf32.f32 %0, %1;" : "=r"(r) : "f"(x));
    return r;
}

__device__ __forceinline__ void mma_tf32(float c[4],
                                         unsigned a0, unsigned a1, unsigned a2, unsigned a3,
                                         unsigned b0, unsigned b1) {
    asm volatile(
        "mma.sync.aligned.m16n8k8.row.col.f32.tf32.tf32.f32 "
        "{%0,%1,%2,%3}, {%4,%5,%6,%7}, {%8,%9}, {%0,%1,%2,%3};"
        : "+f"(c[0]), "+f"(c[1]), "+f"(c[2]), "+f"(c[3])
        : "r"(a0), "r"(a1), "r"(a2), "r"(a3), "r"(b0), "r"(b1));
}

// ---------------------------------------------------------------
// 1. zero degree (int4)
__global__ void zero_deg_kernel() {
    int i = blockIdx.x * blockDim.x + threadIdx.x;
    if (i < NN / 4) ((int4*)g_deg)[i] = make_int4(0, 0, 0, 0);
}

// 2. degree histogram (in-degree over dst), 4 edges/thread
__global__ void count_deg_kernel(const int* __restrict__ dst) {
    int e = blockIdx.x * blockDim.x + threadIdx.x;
    if (e < EE / 4) {
        int4 d = ((const int4*)dst)[e];
        atomicAdd(&g_deg[d.x], 1);
        atomicAdd(&g_deg[d.y], 1);
        atomicAdd(&g_deg[d.z], 1);
        atomicAdd(&g_deg[d.w], 1);
    }
}

// 3. single-block exclusive scan over 40000 counts + norms.
__global__ void scan_build_kernel() {
    __shared__ int partials[1024];
    const int tid = threadIdx.x;
    const int CH  = (NN + 1023) / 1024;   // 40
    const int start = tid * CH;

    int sum = 0;
    for (int i = 0; i < CH; i++) {
        int idx = start + i;
        if (idx < NN) sum += g_deg[idx];
    }
    partials[tid] = sum;
    __syncthreads();

    for (int off = 1; off < 1024; off <<= 1) {
        int v = 0;
        if (tid >= off) v = partials[tid - off];
        __syncthreads();
        partials[tid] += v;
        __syncthreads();
    }

    int run = (tid > 0) ? partials[tid - 1] : 0;
    for (int i = 0; i < CH; i++) {
        int idx = start + i;
        if (idx < NN) {
            g_rowptr[idx] = run;
            g_cur[idx]    = run;
            int d = g_deg[idx];
            run += d;
            float dn = fmaxf((float)d, 1.0f);
            float nv = rsqrtf(dn);
            g_norm[idx]  = nv;
            g_norm2[idx] = nv * nv;
        }
    }
    if (tid == 0) g_rowptr[NN] = partials[1023];
}

// 4. fill CSR column indices, 4 edges/thread
__global__ void fill_csr_kernel(const int* __restrict__ src,
                                const int* __restrict__ dst) {
    int e = blockIdx.x * blockDim.x + threadIdx.x;
    if (e < EE / 4) {
        int4 s = ((const int4*)src)[e];
        int4 d = ((const int4*)dst)[e];
        g_colidx[atomicAdd(&g_cur[d.x], 1)] = s.x;
        g_colidx[atomicAdd(&g_cur[d.y], 1)] = s.y;
        g_colidx[atomicAdd(&g_cur[d.z], 1)] = s.z;
        g_colidx[atomicAdd(&g_cur[d.w], 1)] = s.w;
    }
}

// 5. feature pre-scale to fp16: feat_h[row] = half(norm[row] * X[row])
__global__ void conv_feat_kernel(const float* __restrict__ X) {
    int i = blockIdx.x * blockDim.x + threadIdx.x;   // one half2 each
    if (i < NN * (FIN / 2)) {
        int row = i >> 6;
        float2 v = ((const float2*)X)[i];
        float nv = g_norm[row];
        ((__half2*)g_feat_h)[i] = __floats2half2_rn(v.x * nv, v.y * nv);
    }
}

// 6. propagation hop on fp16 rows: warp per dst node, lane = 4 halves (8B).
//    acc = sum_{(s->w)} hin_h[s]; out = oscale[w] * acc  (fp16 or fp32 out)
template <bool HALF_OUT>
__global__ void hop_h_kernel(const __half* __restrict__ hin,
                             void* __restrict__ hout,
                             const float* __restrict__ oscale) {
    int w    = (blockIdx.x * blockDim.x + threadIdx.x) >> 5;
    int lane = threadIdx.x & 31;
    if (w >= NN) return;

    int j  = g_rowptr[w];
    int je = g_rowptr[w + 1];

    const uint2* hin2 = (const uint2*)hin;   // 32 uint2 (4 halves) per row
    float4 acc = make_float4(0.f, 0.f, 0.f, 0.f);

    for (; j + 2 <= je; j += 2) {
        int s0 = __ldg(&g_colidx[j]);
        int s1 = __ldg(&g_colidx[j + 1]);
        uint2 v0 = hin2[s0 * 32 + lane];
        uint2 v1 = hin2[s1 * 32 + lane];
        float2 a0 = __half22float2(*(__half2*)&v0.x);
        float2 a1 = __half22float2(*(__half2*)&v0.y);
        float2 b0 = __half22float2(*(__half2*)&v1.x);
        float2 b1 = __half22float2(*(__half2*)&v1.y);
        acc.x += a0.x + b0.x;
        acc.y += a0.y + b0.y;
        acc.z += a1.x + b1.x;
        acc.w += a1.y + b1.y;
    }
    if (j < je) {
        int s0 = __ldg(&g_colidx[j]);
        uint2 v0 = hin2[s0 * 32 + lane];
        float2 a0 = __half22float2(*(__half2*)&v0.x);
        float2 a1 = __half22float2(*(__half2*)&v0.y);
        acc.x += a0.x; acc.y += a0.y; acc.z += a1.x; acc.w += a1.y;
    }

    float os = oscale[w];
    acc.x *= os; acc.y *= os; acc.z *= os; acc.w *= os;

    if (HALF_OUT) {
        uint2 o;
        *(__half2*)&o.x = __floats2half2_rn(acc.x, acc.y);
        *(__half2*)&o.y = __floats2half2_rn(acc.z, acc.w);
        ((uint2*)hout)[w * 32 + lane] = o;
    } else {
        ((float4*)hout)[w * 32 + lane] = acc;
    }
}

// ---------------------------------------------------------------
// 7. Fused MLP head (tf32 tensor cores):
//    out = relu(A @ W1 + b1) @ W2 + b2,  A=[N,128], W1=[128,256], W2=[256,40]
//    block = 256 thr = 8 warps, tile M=64. Phase1: 64x256 H in registers.
//    Phase2: H bounced through smem in 64-col chunks into second mma.
#define AS_STRIDE 36    // %32==4 -> conflict-free A frag loads
#define BS_STRIDE 264   // %32==8 -> conflict-free B frag loads
#define HS_STRIDE 68    // %32==4 -> conflict-free A frag loads (phase 2)

__global__ __launch_bounds__(256) void gemm12_mma(const float* __restrict__ A,
                                                  const float* __restrict__ W1,
                                                  const float* __restrict__ b1,
                                                  const float* __restrict__ W2,
                                                  const float* __restrict__ b2,
                                                  float* __restrict__ out) {
    __shared__ float SP[64 * AS_STRIDE + 32 * BS_STRIDE];   // 10752 floats = 42 KB
    float* As = SP;                       // phase 1
    float* Bs = SP + 64 * AS_STRIDE;
    float* Hs = SP;                       // phase 2 (aliases, after sync)
    float* Ws = SP + 64 * HS_STRIDE;      // 64x40

    const int tid  = threadIdx.x;
    const int lane = tid & 31;
    const int warp = tid >> 5;
    const int wm   = warp >> 2;        // 0..1 : phase1 m32 band
    const int wn   = warp & 3;         // 0..3 : phase1 n64 band
    const int row0 = blockIdx.x * 64;
    const int g    = lane >> 2;        // 0..7
    const int tk   = lane & 3;         // 0..3

    float c[2][8][4];
#pragma unroll
    for (int i = 0; i < 2; i++)
#pragma unroll
        for (int jj = 0; jj < 8; jj++)
#pragma unroll
            for (int q = 0; q < 4; q++) c[i][jj][q] = 0.f;

    // ---------------- phase 1: H = A @ W1 ----------------
    for (int kk = 0; kk < 4; kk++) {
#pragma unroll
        for (int l = 0; l < 2; l++) {
            int f  = tid + l * 256;
            int r  = f >> 3;
            int c4 = (f & 7) * 4;
            float4 v = *(const float4*)(A + (row0 + r) * FIN + kk * 32 + c4);
            float* dstp = &As[r * AS_STRIDE + c4];
            dstp[0] = __uint_as_float(f2tf32(v.x));
            dstp[1] = __uint_as_float(f2tf32(v.y));
            dstp[2] = __uint_as_float(f2tf32(v.z));
            dstp[3] = __uint_as_float(f2tf32(v.w));
        }
#pragma unroll
        for (int l = 0; l < 8; l++) {
            int f  = tid + l * 256;
            int r  = f >> 6;
            int c4 = (f & 63) * 4;
            float4 v = *(const float4*)(W1 + (kk * 32 + r) * FHID + c4);
            float* dstp = &Bs[r * BS_STRIDE + c4];
            dstp[0] = __uint_as_float(f2tf32(v.x));
            dstp[1] = __uint_as_float(f2tf32(v.y));
            dstp[2] = __uint_as_float(f2tf32(v.z));
            dstp[3] = __uint_as_float(f2tf32(v.w));
        }
        __syncthreads();

#pragma unroll
        for (int k8 = 0; k8 < 4; k8++) {
            int kl = k8 * 8 + tk;
            unsigned a[2][4];
#pragma unroll
            for (int mt = 0; mt < 2; mt++) {
                int rb = wm * 32 + mt * 16 + g;
                a[mt][0] = __float_as_uint(As[rb * AS_STRIDE + kl]);
                a[mt][1] = __float_as_uint(As[(rb + 8) * AS_STRIDE + kl]);
                a[mt][2] = __float_as_uint(As[rb * AS_STRIDE + kl + 4]);
                a[mt][3] = __float_as_uint(As[(rb + 8) * AS_STRIDE + kl + 4]);
            }
            unsigned b[8][2];
#pragma unroll
            for (int nt = 0; nt < 8; nt++) {
                int n = wn * 64 + nt * 8 + g;
                b[nt][0] = __float_as_uint(Bs[kl * BS_STRIDE + n]);
                b[nt][1] = __float_as_uint(Bs[(kl + 4) * BS_STRIDE + n]);
            }
#pragma unroll
            for (int mt = 0; mt < 2; mt++)
#pragma unroll
                for (int nt = 0; nt < 8; nt++)
                    mma_tf32(c[mt][nt], a[mt][0], a[mt][1], a[mt][2], a[mt][3],
                             b[nt][0], b[nt][1]);
        }
        __syncthreads();
    }

    // ---------------- phase 2: out = relu(H + b1) @ W2 + b2 ----------------
    const int half2nd = warp >> 2;     // 0..1 : split of 5 n8 tiles (3 / 2)
    const int band    = warp & 3;      // 0..3 : m16 band
    const int NT0     = half2nd * 3;
    const int NTN     = half2nd ? 2 : 3;

    float cacc[3][4];
#pragma unroll
    for (int t = 0; t < 3; t++)
#pragma unroll
        for (int q = 0; q < 4; q++) cacc[t][q] = 0.f;

    for (int kk2 = 0; kk2 < 4; kk2++) {
        // stage W2 chunk: rows [kk2*64, kk2*64+64), all 40 cols (640 float4s)
#pragma unroll
        for (int l = 0; l < 3; l++) {
            int f = tid + l * 256;
            if (f < 640) {
                int r  = f / 10;
                int c4 = (f % 10) * 4;
                float4 v = *(const float4*)(W2 + (kk2 * 64 + r) * FCLS + c4);
                float* dstp = &Ws[r * FCLS + c4];
                dstp[0] = __uint_as_float(f2tf32(v.x));
                dstp[1] = __uint_as_float(f2tf32(v.y));
                dstp[2] = __uint_as_float(f2tf32(v.z));
                dstp[3] = __uint_as_float(f2tf32(v.w));
            }
        }
        // warps owning H cols [kk2*64, +64) deposit bias+relu+tf32 into Hs
        if (wn == kk2) {
#pragma unroll
            for (int mt = 0; mt < 2; mt++) {
                int r0 = wm * 32 + mt * 16 + g;
#pragma unroll
                for (int nt = 0; nt < 8; nt++) {
                    int cl  = nt * 8 + tk * 2;
                    float bb0 = b1[kk2 * 64 + cl];
                    float bb1 = b1[kk2 * 64 + cl + 1];
                    Hs[r0 * HS_STRIDE + cl]           = __uint_as_float(f2tf32(fmaxf(c[mt][nt][0] + bb0, 0.f)));
                    Hs[r0 * HS_STRIDE + cl + 1]       = __uint_as_float(f2tf32(fmaxf(c[mt][nt][1] + bb1, 0.f)));
                    Hs[(r0 + 8) * HS_STRIDE + cl]     = __uint_as_float(f2tf32(fmaxf(c[mt][nt][2] + bb0, 0.f)));
                    Hs[(r0 + 8) * HS_STRIDE + cl + 1] = __uint_as_float(f2tf32(fmaxf(c[mt][nt][3] + bb1, 0.f)));
                }
            }
        }
        __syncthreads();

#pragma unroll
        for (int k8 = 0; k8 < 8; k8++) {
            int kl = k8 * 8 + tk;
            int rb = band * 16 + g;
            unsigned a0 = __float_as_uint(Hs[rb * HS_STRIDE + kl]);
            unsigned a1 = __float_as_uint(Hs[(rb + 8) * HS_STRIDE + kl]);
            unsigned a2 = __float_as_uint(Hs[rb * HS_STRIDE + kl + 4]);
            unsigned a3 = __float_as_uint(Hs[(rb + 8) * HS_STRIDE + kl + 4]);
#pragma unroll
            for (int t = 0; t < 3; t++) {
                if (t < NTN) {
                    int n = (NT0 + t) * 8 + g;
                    unsigned b0 = __float_as_uint(Ws[kl * FCLS + n]);
                    unsigned b1f = __float_as_uint(Ws[(kl + 4) * FCLS + n]);
                    mma_tf32(cacc[t], a0, a1, a2, a3, b0, b1f);
                }
            }
        }
        __syncthreads();
    }

    // epilogue
    int r0 = row0 + band * 16 + g;
#pragma unroll
    for (int t = 0; t < 3; t++) {
        if (t < NTN) {
            int col = (NT0 + t) * 8 + tk * 2;
            float bb0 = b2[col], bb1 = b2[col + 1];
            *(float2*)(out + r0 * FCLS + col) =
                make_float2(cacc[t][0] + bb0, cacc[t][1] + bb1);
            *(float2*)(out + (r0 + 8) * FCLS + col) =
                make_float2(cacc[t][2] + bb0, cacc[t][3] + bb1);
        }
    }
}

// ---------------------------------------------------------------
extern "C" void kernel_launch(void* const* d_in, const int* in_sizes, int n_in,
                              void* d_out, int out_size) {
    const float* features = (const float*)d_in[0];
    const int*   src      = (const int*)d_in[1];
    const int*   dst      = (const int*)d_in[2];
    const float* W1       = (const float*)d_in[3];
    const float* b1       = (const float*)d_in[4];
    const float* W2       = (const float*)d_in[5];
    const float* b2       = (const float*)d_in[6];
    float*       out      = (float*)d_out;

    __half *feat_h, *buf1h;
    float *buf2, *norm, *norm2;
    cudaGetSymbolAddress((void**)&feat_h, g_feat_h);
    cudaGetSymbolAddress((void**)&buf1h,  g_buf1h);
    cudaGetSymbolAddress((void**)&buf2,   g_buf2);
    cudaGetSymbolAddress((void**)&norm,   g_norm);
    cudaGetSymbolAddress((void**)&norm2,  g_norm2);

    // CSR build
    zero_deg_kernel<<<(NN / 4 + 255) / 256, 256>>>();
    count_deg_kernel<<<(EE / 4 + 255) / 256, 256>>>(dst);
    scan_build_kernel<<<1, 1024>>>();
    fill_csr_kernel<<<(EE / 4 + 255) / 256, 256>>>(src, dst);

    // feat_h = half(norm * X)   (needs norm from scan_build)
    conv_feat_kernel<<<(NN * (FIN / 2) + 255) / 256, 256>>>(features);

    // hop1: buf1h = half(norm^2 * A feat_h);  hop2: buf2 = norm * A buf1h
    hop_h_kernel<true ><<<(NN * 32 + 255) / 256, 256>>>(feat_h, buf1h, norm2);
    hop_h_kernel<false><<<(NN * 32 + 255) / 256, 256>>>(buf1h, buf2, norm);

    // fused MLP head on tensor cores (tf32)
    gemm12_mma<<<NN / 64, 256>>>(buf2, W1, b1, W2, b2, out);
}

// round 5
// speedup vs baseline: 3.0429x; 1.9222x over previous
#include <cuda_runtime.h>
#include <cuda_fp16.h>
#include <cstdint>

#define NN   40000
#define EE   640000
#define FIN  128
#define FHID 256
#define FCLS 40

#define SCAN_BLK 256
#define NSB ((NN + SCAN_BLK - 1) / SCAN_BLK)   // 157

// ---- scratch (no allocation allowed -> __device__ globals) ----
__device__ int    g_deg[NN];
__device__ int    g_rowptr[NN + 1];
__device__ int    g_cur[NN];
__device__ int    g_colidx[EE];
__device__ int    g_bsum[NSB];
__device__ int    g_bbase[NSB];
__device__ float  g_norm[NN];
__device__ float  g_norm2[NN];
__device__ __half g_feat_h[NN * FIN];   // norm * X      (fp16)
__device__ __half g_buf1h[NN * FIN];    // N^2 A N X     (fp16)
__device__ float  g_buf2[NN * FIN];     // N A N^2 A N X (fp32, GEMM input)

// ---------------------------------------------------------------
__device__ __forceinline__ unsigned f2tf32(float x) {
    unsigned r;
    asm("cvt.rna.tf32.f32 %0, %1;" : "=r"(r) : "f"(x));
    return r;
}

__device__ __forceinline__ void mma_tf32(float c[4],
                                         unsigned a0, unsigned a1, unsigned a2, unsigned a3,
                                         unsigned b0, unsigned b1) {
    asm volatile(
        "mma.sync.aligned.m16n8k8.row.col.f32.tf32.tf32.f32 "
        "{%0,%1,%2,%3}, {%4,%5,%6,%7}, {%8,%9}, {%0,%1,%2,%3};"
        : "+f"(c[0]), "+f"(c[1]), "+f"(c[2]), "+f"(c[3])
        : "r"(a0), "r"(a1), "r"(a2), "r"(a3), "r"(b0), "r"(b1));
}

// ---------------------------------------------------------------
// degree histogram (in-degree over dst), 4 edges/thread
__global__ void count_deg_kernel(const int* __restrict__ dst) {
    int e = blockIdx.x * blockDim.x + threadIdx.x;
    if (e < EE / 4) {
        int4 d = ((const int4*)dst)[e];
        atomicAdd(&g_deg[d.x], 1);
        atomicAdd(&g_deg[d.y], 1);
        atomicAdd(&g_deg[d.z], 1);
        atomicAdd(&g_deg[d.w], 1);
    }
}

// ---- 3-phase parallel scan over degrees ----
__global__ void scan_phase1() {            // grid NSB, block 256: block sums
    __shared__ int wsum[8];
    int tid = threadIdx.x, w = tid >> 5, l = tid & 31;
    int i = blockIdx.x * SCAN_BLK + tid;
    int s = (i < NN) ? g_deg[i] : 0;
#pragma unroll
    for (int o = 16; o; o >>= 1) s += __shfl_down_sync(~0u, s, o);
    if (l == 0) wsum[w] = s;
    __syncthreads();
    if (tid == 0) {
        int t = 0;
#pragma unroll
        for (int k = 0; k < 8; k++) t += wsum[k];
        g_bsum[blockIdx.x] = t;
    }
}

__global__ void scan_phase2() {            // 1 block, 256 threads: scan NSB sums
    __shared__ int sh[256];
    int tid = threadIdx.x;
    int v = (tid < NSB) ? g_bsum[tid] : 0;
    sh[tid] = v;
    __syncthreads();
    for (int o = 1; o < 256; o <<= 1) {
        int t = 0;
        if (tid >= o) t = sh[tid - o];
        __syncthreads();
        sh[tid] += t;
        __syncthreads();
    }
    if (tid < NSB) g_bbase[tid] = sh[tid] - v;   // exclusive base
}

__global__ void scan_phase3() {            // grid NSB: fill rowptr/cur/norms
    __shared__ int ws[8];
    int tid = threadIdx.x, w = tid >> 5, l = tid & 31;
    int i = blockIdx.x * SCAN_BLK + tid;
    int v = (i < NN) ? g_deg[i] : 0;
    int incl = v;
#pragma unroll
    for (int o = 1; o < 32; o <<= 1) {
        int t = __shfl_up_sync(~0u, incl, o);
        if (l >= o) incl += t;
    }
    if (l == 31) ws[w] = incl;
    __syncthreads();
    if (tid < 8) {
        int t = ws[tid];
#pragma unroll
        for (int o = 1; o < 8; o <<= 1) {
            int u = __shfl_up_sync(0xffu, t, o);
            if (tid >= o) t += u;
        }
        ws[tid] = t;
    }
    __syncthreads();
    int excl = g_bbase[blockIdx.x] + ((w > 0) ? ws[w - 1] : 0) + incl - v;
    if (i < NN) {
        g_rowptr[i] = excl;
        g_cur[i]    = excl;
        float dn = fmaxf((float)v, 1.0f);
        float nv = rsqrtf(dn);
        g_norm[i]  = nv;
        g_norm2[i] = nv * nv;
        if (i == NN - 1) g_rowptr[NN] = excl + v;
    }
}

// fill CSR column indices, 4 edges/thread
__global__ void fill_csr_kernel(const int* __restrict__ src,
                                const int* __restrict__ dst) {
    int e = blockIdx.x * blockDim.x + threadIdx.x;
    if (e < EE / 4) {
        int4 s = ((const int4*)src)[e];
        int4 d = ((const int4*)dst)[e];
        g_colidx[atomicAdd(&g_cur[d.x], 1)] = s.x;
        g_colidx[atomicAdd(&g_cur[d.y], 1)] = s.y;
        g_colidx[atomicAdd(&g_cur[d.z], 1)] = s.z;
        g_colidx[atomicAdd(&g_cur[d.w], 1)] = s.w;
    }
}

// feature pre-scale to fp16: feat_h[row] = half(norm[row] * X[row])
__global__ void conv_feat_kernel(const float* __restrict__ X) {
    int i = blockIdx.x * blockDim.x + threadIdx.x;   // one half2 each
    if (i < NN * (FIN / 2)) {
        int row = i >> 6;
        float2 v = ((const float2*)X)[i];
        float nv = g_norm[row];
        ((__half2*)g_feat_h)[i] = __floats2half2_rn(v.x * nv, v.y * nv);
    }
}

// ---------------------------------------------------------------
// propagation hop, fp16 rows, MLP=4: warp per dst node, lane = 4 halves (8B).
// acc = sum_{(s->w)} hin_h[s]; out = oscale[w] * acc
template <bool HALF_OUT>
__global__ void hop_h_kernel(const __half* __restrict__ hin,
                             void* __restrict__ hout,
                             const float* __restrict__ oscale) {
    int w    = (blockIdx.x * blockDim.x + threadIdx.x) >> 5;
    int lane = threadIdx.x & 31;
    if (w >= NN) return;

    int j  = g_rowptr[w];
    int je = g_rowptr[w + 1];

    const uint2* hin2 = (const uint2*)hin;   // 32 uint2 (4 halves) per row
    float4 accA = make_float4(0.f, 0.f, 0.f, 0.f);
    float4 accB = make_float4(0.f, 0.f, 0.f, 0.f);

    for (; j + 4 <= je; j += 4) {
        int s0 = __ldg(&g_colidx[j]);
        int s1 = __ldg(&g_colidx[j + 1]);
        int s2 = __ldg(&g_colidx[j + 2]);
        int s3 = __ldg(&g_colidx[j + 3]);
        uint2 v0 = hin2[s0 * 32 + lane];
        uint2 v1 = hin2[s1 * 32 + lane];
        uint2 v2 = hin2[s2 * 32 + lane];
        uint2 v3 = hin2[s3 * 32 + lane];
        float2 a0 = __half22float2(*(__half2*)&v0.x);
        float2 a1 = __half22float2(*(__half2*)&v0.y);
        float2 b0 = __half22float2(*(__half2*)&v1.x);
        float2 b1 = __half22float2(*(__half2*)&v1.y);
        float2 c0 = __half22float2(*(__half2*)&v2.x);
        float2 c1 = __half22float2(*(__half2*)&v2.y);
        float2 d0 = __half22float2(*(__half2*)&v3.x);
        float2 d1 = __half22float2(*(__half2*)&v3.y);
        accA.x += a0.x + b0.x;  accB.x += c0.x + d0.x;
        accA.y += a0.y + b0.y;  accB.y += c0.y + d0.y;
        accA.z += a1.x + b1.x;  accB.z += c1.x + d1.x;
        accA.w += a1.y + b1.y;  accB.w += c1.y + d1.y;
    }
    if (j + 2 <= je) {
        int s0 = __ldg(&g_colidx[j]);
        int s1 = __ldg(&g_colidx[j + 1]);
        uint2 v0 = hin2[s0 * 32 + lane];
        uint2 v1 = hin2[s1 * 32 + lane];
        float2 a0 = __half22float2(*(__half2*)&v0.x);
        float2 a1 = __half22float2(*(__half2*)&v0.y);
        float2 b0 = __half22float2(*(__half2*)&v1.x);
        float2 b1 = __half22float2(*(__half2*)&v1.y);
        accA.x += a0.x + b0.x;
        accA.y += a0.y + b0.y;
        accA.z += a1.x + b1.x;
        accA.w += a1.y + b1.y;
        j += 2;
    }
    if (j < je) {
        int s0 = __ldg(&g_colidx[j]);
        uint2 v0 = hin2[s0 * 32 + lane];
        float2 a0 = __half22float2(*(__half2*)&v0.x);
        float2 a1 = __half22float2(*(__half2*)&v0.y);
        accB.x += a0.x; accB.y += a0.y; accB.z += a1.x; accB.w += a1.y;
    }

    float os = oscale[w];
    float4 acc;
    acc.x = (accA.x + accB.x) * os;
    acc.y = (accA.y + accB.y) * os;
    acc.z = (accA.z + accB.z) * os;
    acc.w = (accA.w + accB.w) * os;

    if (HALF_OUT) {
        uint2 o;
        *(__half2*)&o.x = __floats2half2_rn(acc.x, acc.y);
        *(__half2*)&o.y = __floats2half2_rn(acc.z, acc.w);
        ((uint2*)hout)[w * 32 + lane] = o;
    } else {
        ((float4*)hout)[w * 32 + lane] = acc;
    }
}

// ---------------------------------------------------------------
// Fused MLP head (tf32 tensor cores):
// out = relu(A @ W1 + b1) @ W2 + b2,  A=[N,128], W1=[128,256], W2=[256,40]
#define AS_STRIDE 36    // %32==4 -> conflict-free A frag loads
#define BS_STRIDE 264   // %32==8 -> conflict-free B frag loads
#define HS_STRIDE 68    // %32==4 -> conflict-free A frag loads (phase 2)

__global__ __launch_bounds__(256) void gemm12_mma(const float* __restrict__ A,
                                                  const float* __restrict__ W1,
                                                  const float* __restrict__ b1,
                                                  const float* __restrict__ W2,
                                                  const float* __restrict__ b2,
                                                  float* __restrict__ out) {
    __shared__ float SP[64 * AS_STRIDE + 32 * BS_STRIDE];   // 42 KB
    float* As = SP;                       // phase 1
    float* Bs = SP + 64 * AS_STRIDE;
    float* Hs = SP;                       // phase 2 (aliases, after sync)
    float* Ws = SP + 64 * HS_STRIDE;      // 64x40

    const int tid  = threadIdx.x;
    const int lane = tid & 31;
    const int warp = tid >> 5;
    const int wm   = warp >> 2;        // 0..1 : phase1 m32 band
    const int wn   = warp & 3;         // 0..3 : phase1 n64 band
    const int row0 = blockIdx.x * 64;
    const int g    = lane >> 2;        // 0..7
    const int tk   = lane & 3;         // 0..3

    float c[2][8][4];
#pragma unroll
    for (int i = 0; i < 2; i++)
#pragma unroll
        for (int jj = 0; jj < 8; jj++)
#pragma unroll
            for (int q = 0; q < 4; q++) c[i][jj][q] = 0.f;

    // ---------------- phase 1: H = A @ W1 ----------------
    for (int kk = 0; kk < 4; kk++) {
#pragma unroll
        for (int l = 0; l < 2; l++) {
            int f  = tid + l * 256;
            int r  = f >> 3;
            int c4 = (f & 7) * 4;
            float4 v = *(const float4*)(A + (row0 + r) * FIN + kk * 32 + c4);
            float* dstp = &As[r * AS_STRIDE + c4];
            dstp[0] = __uint_as_float(f2tf32(v.x));
            dstp[1] = __uint_as_float(f2tf32(v.y));
            dstp[2] = __uint_as_float(f2tf32(v.z));
            dstp[3] = __uint_as_float(f2tf32(v.w));
        }
#pragma unroll
        for (int l = 0; l < 8; l++) {
            int f  = tid + l * 256;
            int r  = f >> 6;
            int c4 = (f & 63) * 4;
            float4 v = *(const float4*)(W1 + (kk * 32 + r) * FHID + c4);
            float* dstp = &Bs[r * BS_STRIDE + c4];
            dstp[0] = __uint_as_float(f2tf32(v.x));
            dstp[1] = __uint_as_float(f2tf32(v.y));
            dstp[2] = __uint_as_float(f2tf32(v.z));
            dstp[3] = __uint_as_float(f2tf32(v.w));
        }
        __syncthreads();

#pragma unroll
        for (int k8 = 0; k8 < 4; k8++) {
            int kl = k8 * 8 + tk;
            unsigned a[2][4];
#pragma unroll
            for (int mt = 0; mt < 2; mt++) {
                int rb = wm * 32 + mt * 16 + g;
                a[mt][0] = __float_as_uint(As[rb * AS_STRIDE + kl]);
                a[mt][1] = __float_as_uint(As[(rb + 8) * AS_STRIDE + kl]);
                a[mt][2] = __float_as_uint(As[rb * AS_STRIDE + kl + 4]);
                a[mt][3] = __float_as_uint(As[(rb + 8) * AS_STRIDE + kl + 4]);
            }
            unsigned b[8][2];
#pragma unroll
            for (int nt = 0; nt < 8; nt++) {
                int n = wn * 64 + nt * 8 + g;
                b[nt][0] = __float_as_uint(Bs[kl * BS_STRIDE + n]);
                b[nt][1] = __float_as_uint(Bs[(kl + 4) * BS_STRIDE + n]);
            }
#pragma unroll
            for (int mt = 0; mt < 2; mt++)
#pragma unroll
                for (int nt = 0; nt < 8; nt++)
                    mma_tf32(c[mt][nt], a[mt][0], a[mt][1], a[mt][2], a[mt][3],
                             b[nt][0], b[nt][1]);
        }
        __syncthreads();
    }

    // ---------------- phase 2: out = relu(H + b1) @ W2 + b2 ----------------
    const int half2nd = warp >> 2;     // 0..1 : split of 5 n8 tiles (3 / 2)
    const int band    = warp & 3;      // 0..3 : m16 band
    const int NT0     = half2nd * 3;
    const int NTN     = half2nd ? 2 : 3;

    float cacc[3][4];
#pragma unroll
    for (int t = 0; t < 3; t++)
#pragma unroll
        for (int q = 0; q < 4; q++) cacc[t][q] = 0.f;

    for (int kk2 = 0; kk2 < 4; kk2++) {
        // stage W2 chunk: rows [kk2*64, +64), all 40 cols (640 float4s)
#pragma unroll
        for (int l = 0; l < 3; l++) {
            int f = tid + l * 256;
            if (f < 640) {
                int r  = f / 10;
                int c4 = (f % 10) * 4;
                float4 v = *(const float4*)(W2 + (kk2 * 64 + r) * FCLS + c4);
                float* dstp = &Ws[r * FCLS + c4];
                dstp[0] = __uint_as_float(f2tf32(v.x));
                dstp[1] = __uint_as_float(f2tf32(v.y));
                dstp[2] = __uint_as_float(f2tf32(v.z));
                dstp[3] = __uint_as_float(f2tf32(v.w));
            }
        }
        // warps owning H cols [kk2*64, +64) deposit bias+relu+tf32 into Hs
        if (wn == kk2) {
#pragma unroll
            for (int mt = 0; mt < 2; mt++) {
                int r0 = wm * 32 + mt * 16 + g;
#pragma unroll
                for (int nt = 0; nt < 8; nt++) {
                    int cl  = nt * 8 + tk * 2;
                    float bb0 = b1[kk2 * 64 + cl];
                    float bb1 = b1[kk2 * 64 + cl + 1];
                    Hs[r0 * HS_STRIDE + cl]           = __uint_as_float(f2tf32(fmaxf(c[mt][nt][0] + bb0, 0.f)));
                    Hs[r0 * HS_STRIDE + cl + 1]       = __uint_as_float(f2tf32(fmaxf(c[mt][nt][1] + bb1, 0.f)));
                    Hs[(r0 + 8) * HS_STRIDE + cl]     = __uint_as_float(f2tf32(fmaxf(c[mt][nt][2] + bb0, 0.f)));
                    Hs[(r0 + 8) * HS_STRIDE + cl + 1] = __uint_as_float(f2tf32(fmaxf(c[mt][nt][3] + bb1, 0.f)));
                }
            }
        }
        __syncthreads();

#pragma unroll
        for (int k8 = 0; k8 < 8; k8++) {
            int kl = k8 * 8 + tk;
            int rb = band * 16 + g;
            unsigned a0 = __float_as_uint(Hs[rb * HS_STRIDE + kl]);
            unsigned a1 = __float_as_uint(Hs[(rb + 8) * HS_STRIDE + kl]);
            unsigned a2 = __float_as_uint(Hs[rb * HS_STRIDE + kl + 4]);
            unsigned a3 = __float_as_uint(Hs[(rb + 8) * HS_STRIDE + kl + 4]);
#pragma unroll
            for (int t = 0; t < 3; t++) {
                if (t < NTN) {
                    int n = (NT0 + t) * 8 + g;
                    unsigned b0  = __float_as_uint(Ws[kl * FCLS + n]);
                    unsigned b1f = __float_as_uint(Ws[(kl + 4) * FCLS + n]);
                    mma_tf32(cacc[t], a0, a1, a2, a3, b0, b1f);
                }
            }
        }
        __syncthreads();
    }

    // epilogue
    int r0 = row0 + band * 16 + g;
#pragma unroll
    for (int t = 0; t < 3; t++) {
        if (t < NTN) {
            int col = (NT0 + t) * 8 + tk * 2;
            float bb0 = b2[col], bb1 = b2[col + 1];
            *(float2*)(out + r0 * FCLS + col) =
                make_float2(cacc[t][0] + bb0, cacc[t][1] + bb1);
            *(float2*)(out + (r0 + 8) * FCLS + col) =
                make_float2(cacc[t][2] + bb0, cacc[t][3] + bb1);
        }
    }
}

// ---------------------------------------------------------------
extern "C" void kernel_launch(void* const* d_in, const int* in_sizes, int n_in,
                              void* d_out, int out_size) {
    const float* features = (const float*)d_in[0];
    const int*   src      = (const int*)d_in[1];
    const int*   dst      = (const int*)d_in[2];
    const float* W1       = (const float*)d_in[3];
    const float* b1       = (const float*)d_in[4];
    const float* W2       = (const float*)d_in[5];
    const float* b2       = (const float*)d_in[6];
    float*       out      = (float*)d_out;

    __half *feat_h, *buf1h;
    float *buf2, *norm, *norm2;
    int   *degp;
    cudaGetSymbolAddress((void**)&feat_h, g_feat_h);
    cudaGetSymbolAddress((void**)&buf1h,  g_buf1h);
    cudaGetSymbolAddress((void**)&buf2,   g_buf2);
    cudaGetSymbolAddress((void**)&norm,   g_norm);
    cudaGetSymbolAddress((void**)&norm2,  g_norm2);
    cudaGetSymbolAddress((void**)&degp,   g_deg);

    // CSR build
    cudaMemsetAsync(degp, 0, NN * sizeof(int));
    count_deg_kernel<<<(EE / 4 + 255) / 256, 256>>>(dst);
    scan_phase1<<<NSB, SCAN_BLK>>>();
    scan_phase2<<<1, 256>>>();
    scan_phase3<<<NSB, SCAN_BLK>>>();
    fill_csr_kernel<<<(EE / 4 + 255) / 256, 256>>>(src, dst);

    // feat_h = half(norm * X)
    conv_feat_kernel<<<(NN * (FIN / 2) + 255) / 256, 256>>>(features);

    // hop1: buf1h = half(norm^2 * A feat_h);  hop2: buf2 = norm * A buf1h
    hop_h_kernel<true ><<<(NN * 32 + 255) / 256, 256>>>(feat_h, buf1h, norm2);
    hop_h_kernel<false><<<(NN * 32 + 255) / 256, 256>>>(buf1h, buf2, norm);

    // fused MLP head on tensor cores (tf32)
    gemm12_mma<<<NN / 64, 256>>>(buf2, W1, b1, W2, b2, out);
}